// round 8
// baseline (speedup 1.0000x reference)
#include <cuda_runtime.h>
#include <cuda_bf16.h>

#define NN 100000
#define HH 256

// Per-node scratch (device globals: no allocation allowed in kernel_launch)
__device__ float2   g_z[NN];         // z = input @ W  (z0, z1)
__device__ float    g_er[NN];        // z . attn_r (dest term) — separate, read-only
                                     // array: do NOT co-locate with the atomic
                                     // target (R5 showed sector-RMW contention)
__device__ float4   g_acc[NN];       // {denom, num0, num1, pad}
__device__ float    g_sink;          // DCE-blocker for prefetch blocks

// K1: 8-lanes-per-node GEMM [N,256]@[256,2] -> z, er; init accumulators.
// 256 threads = 32 nodes/block, 8 float4 loads per lane (high MLP), 128B
// coalesced per 8-lane group, 3-level shuffle reduction.
__global__ void k_gemm(const float* __restrict__ input,
                       const float* __restrict__ W,
                       const float* __restrict__ attn_r) {
    __shared__ float sw0[HH], sw1[HH];
    int t = threadIdx.x;
    { sw0[t] = W[t * 2 + 0]; sw1[t] = W[t * 2 + 1]; }   // t covers 0..255 == HH
    __syncthreads();

    int grp = t >> 3, gl = t & 7;
    int node = blockIdx.x * 32 + grp;
    if (node >= NN) return;

    const float4* row4 = (const float4*)(input + (size_t)node * HH);
    float d0 = 0.f, d1 = 0.f;
#pragma unroll
    for (int j = 0; j < 8; j++) {
        int k = j * 8 + gl;                  // lanes 0..7 -> contiguous 128B
        float4 v = row4[k];
        int b = 4 * k;
        d0 = fmaf(v.x, sw0[b+0], d0); d1 = fmaf(v.x, sw1[b+0], d1);
        d0 = fmaf(v.y, sw0[b+1], d0); d1 = fmaf(v.y, sw1[b+1], d1);
        d0 = fmaf(v.z, sw0[b+2], d0); d1 = fmaf(v.z, sw1[b+2], d1);
        d0 = fmaf(v.w, sw0[b+3], d0); d1 = fmaf(v.w, sw1[b+3], d1);
    }
#pragma unroll
    for (int o = 4; o; o >>= 1) {
        d0 += __shfl_xor_sync(0xFFFFFFFFu, d0, o);
        d1 += __shfl_xor_sync(0xFFFFFFFFu, d1, o);
    }
    if (gl == 0) {
        g_z[node]   = make_float2(d0, d1);
        g_er[node]  = d0 * attn_r[0] + d1 * attn_r[1];
        g_acc[node] = make_float4(0.f, 0.f, 0.f, 0.f);
    }
}

// K2: hybrid kernel.
//   blocks [0, PF_BLOCKS)          : L2 re-warm of the low PF4 float4s of input
//                                    (k_esum leaves HBM ~idle; k_out will read
//                                    these lines LAST via reverse traversal)
//   blocks [PF_BLOCKS, ...)        : per-edge softmax accumulation WITHOUT
//                                    max-subtraction (shift-invariant; e is far
//                                    inside fp32 exp range). 8 edges/thread,
//                                    evict-first edge streams.
#define PF4       3000000            // 48 MB of input re-warmed
#define PF_PER_T  16
#define PF_BLOCKS ((PF4 / PF_PER_T + 255) / 256)      // 733
__global__ void k_esum_g(const int4* __restrict__ src4, const int4* __restrict__ dst4,
                         int E4, const float* __restrict__ attn_l,
                         const float4* __restrict__ input) {
    if (blockIdx.x < PF_BLOCKS) {
        // ---- prefetch path: touch lines into L2 (skip L1), keep result live
        int t = blockIdx.x * 256 + threadIdx.x;
        float acc = 0.f;
#pragma unroll
        for (int j = 0; j < PF_PER_T; j++) {
            int idx = t * PF_PER_T + j;
            if (idx < PF4) {
                float4 v = __ldcg(&input[idx]);
                acc += v.x + v.y + v.z + v.w;
            }
        }
        if (acc == 1.2345e38f) g_sink = acc;   // never true; blocks DCE
        return;
    }

    float a0 = __ldg(&attn_l[0]);
    float a1 = __ldg(&attn_l[1]);
    int i = (blockIdx.x - PF_BLOCKS) * blockDim.x + threadIdx.x;
    int base = i * 2;
    if (base >= E4) return;

    int4 s0 = __ldcs(&src4[base]);
    int4 d0 = __ldcs(&dst4[base]);
    int4 s1 = __ldcs(&src4[base + 1]);
    int4 d1 = __ldcs(&dst4[base + 1]);

    int ss[8] = {s0.x, s0.y, s0.z, s0.w, s1.x, s1.y, s1.z, s1.w};
    int dd[8] = {d0.x, d0.y, d0.z, d0.w, d1.x, d1.y, d1.z, d1.w};

    float2 z[8];
    float  erd[8];
#pragma unroll
    for (int j = 0; j < 8; j++) {
        z[j]   = __ldg(&g_z[ss[j]]);
        erd[j] = __ldg(&g_er[dd[j]]);
    }
#pragma unroll
    for (int j = 0; j < 8; j++) {
        float e = fmaf(z[j].x, a0, fmaf(z[j].y, a1, erd[j]));
        e = (e > 0.f) ? e : 0.2f * e;        // leaky_relu(0.2)
        float ex = __expf(e);
        atomicAdd(&g_acc[dd[j]], make_float4(ex, ex * z[j].x, ex * z[j].y, 0.f));
    }
}

// K3 (fused epilogue + gate + scale):
// out[i,h] = input[i,h] * sigmoid(x[i]*relu(coff0) + relu(coff1)),
// coff = num/denom + bias recomputed per thread from g_acc (L2-resident).
// CTA order REVERSED: first-scheduled blocks read gemm-warm high addresses,
// last-scheduled read the prefetch-warm low addresses.
#define TOT4 (NN * (HH / 4))                 // 6,400,000 float4s
__global__ void k_out(const float4* __restrict__ input, float4* __restrict__ out,
                      const float* __restrict__ x, const float* __restrict__ bias) {
    const int half = TOT4 / 2;               // 3,200,000
    int b = (int)gridDim.x - 1 - (int)blockIdx.x;      // reverse traversal
    int i = b * (int)blockDim.x + (int)threadIdx.x;
    if (i >= half) return;
    int i2 = i + half;

    float b0 = __ldg(&bias[0]);
    float b1 = __ldg(&bias[1]);

    int r0 = i  >> 6;                        // 64 float4 per row
    int r1 = i2 >> 6;

    float4 v0 = __ldcs(&input[i2]);          // highest addresses first (hotter)
    float4 v1 = __ldcs(&input[i]);
    float4 a0 = __ldg(&g_acc[r1]);
    float4 a1 = __ldg(&g_acc[r0]);
    float  x0 = __ldg(&x[r1]);
    float  x1 = __ldg(&x[r0]);

    float inv0 = 1.f / a0.x;
    float c00 = a0.y * inv0 + b0, c01 = a0.z * inv0 + b1;
    float arg0 = fmaf(x0, fmaxf(c00, 0.f), fmaxf(c01, 0.f));
    float s0 = 1.f / (1.f + __expf(-arg0));

    float inv1 = 1.f / a1.x;
    float c10 = a1.y * inv1 + b0, c11 = a1.z * inv1 + b1;
    float arg1 = fmaf(x1, fmaxf(c10, 0.f), fmaxf(c11, 0.f));
    float s1 = 1.f / (1.f + __expf(-arg1));

    v0.x *= s0; v0.y *= s0; v0.z *= s0; v0.w *= s0;
    v1.x *= s1; v1.y *= s1; v1.z *= s1; v1.w *= s1;
    __stcs(&out[i2], v0);
    __stcs(&out[i],  v1);
}

extern "C" void kernel_launch(void* const* d_in, const int* in_sizes, int n_in,
                              void* d_out, int out_size) {
    const float* input  = (const float*)d_in[0];
    const float* x      = (const float*)d_in[1];
    // d_in[2] = degree (unused)
    const int*   esrc   = (const int*)d_in[3];
    const int*   edst   = (const int*)d_in[4];
    const float* W      = (const float*)d_in[5];
    const float* attn_l = (const float*)d_in[6];
    const float* attn_r = (const float*)d_in[7];
    const float* bias   = (const float*)d_in[8];
    float* out = (float*)d_out;

    int E  = in_sizes[3];
    int E4 = E / 4;            // 800,000 int4s per edge array
    int nE = (E4 + 1) / 2;     // threads processing 2 int4 each
    int eBlocks = (nE + 255) / 256;

    k_gemm<<<(NN + 31) / 32, 256>>>(input, W, attn_r);
    k_esum_g<<<PF_BLOCKS + eBlocks, 256>>>((const int4*)esrc, (const int4*)edst,
                                           E4, attn_l, (const float4*)input);
    k_out<<<(TOT4 / 2 + 255) / 256, 256>>>((const float4*)input, (float4*)out, x, bias);
}

// round 9
// speedup vs baseline: 1.0173x; 1.0173x over previous
#include <cuda_runtime.h>
#include <cuda_bf16.h>

#define NN 100000
#define HH 256

// Per-node scratch (device globals: no allocation allowed in kernel_launch)
__device__ float2   g_z[NN];         // z = input @ W  (z0, z1)
__device__ float    g_er[NN];        // z . attn_r (dest term) — separate, read-only
                                     // array: do NOT co-locate with the atomic
                                     // target (R5 showed sector-RMW contention)
__device__ float4   g_acc[NN];       // {denom, num0, num1, pad}
__device__ float    g_sink;          // DCE-blocker for prefetch blocks

// K1: 8-lanes-per-node GEMM [N,256]@[256,2] -> z, er; init accumulators.
// 256 threads = 32 nodes/block, 8 float4 loads per lane (high MLP), 128B
// coalesced per 8-lane group, 3-level shuffle reduction.
__global__ void k_gemm(const float* __restrict__ input,
                       const float* __restrict__ W,
                       const float* __restrict__ attn_r) {
    __shared__ float sw0[HH], sw1[HH];
    int t = threadIdx.x;
    { sw0[t] = W[t * 2 + 0]; sw1[t] = W[t * 2 + 1]; }   // t covers 0..255 == HH
    __syncthreads();

    int grp = t >> 3, gl = t & 7;
    int node = blockIdx.x * 32 + grp;
    if (node >= NN) return;

    const float4* row4 = (const float4*)(input + (size_t)node * HH);
    float d0 = 0.f, d1 = 0.f;
#pragma unroll
    for (int j = 0; j < 8; j++) {
        int k = j * 8 + gl;                  // lanes 0..7 -> contiguous 128B
        float4 v = row4[k];
        int b = 4 * k;
        d0 = fmaf(v.x, sw0[b+0], d0); d1 = fmaf(v.x, sw1[b+0], d1);
        d0 = fmaf(v.y, sw0[b+1], d0); d1 = fmaf(v.y, sw1[b+1], d1);
        d0 = fmaf(v.z, sw0[b+2], d0); d1 = fmaf(v.z, sw1[b+2], d1);
        d0 = fmaf(v.w, sw0[b+3], d0); d1 = fmaf(v.w, sw1[b+3], d1);
    }
#pragma unroll
    for (int o = 4; o; o >>= 1) {
        d0 += __shfl_xor_sync(0xFFFFFFFFu, d0, o);
        d1 += __shfl_xor_sync(0xFFFFFFFFu, d1, o);
    }
    if (gl == 0) {
        g_z[node]   = make_float2(d0, d1);
        g_er[node]  = d0 * attn_r[0] + d1 * attn_r[1];
        g_acc[node] = make_float4(0.f, 0.f, 0.f, 0.f);
    }
}

// K2: hybrid kernel.
//   blocks [0, PF_BLOCKS)          : L2 re-warm of the low PF4 float4s of input
//                                    (k_esum leaves HBM ~idle; k_out will read
//                                    these lines LAST via reverse traversal)
//   blocks [PF_BLOCKS, ...)        : per-edge softmax accumulation WITHOUT
//                                    max-subtraction (shift-invariant; e is far
//                                    inside fp32 exp range). 8 edges/thread,
//                                    evict-first edge streams.
#define PF4       3000000            // 48 MB of input re-warmed
#define PF_PER_T  16
#define PF_BLOCKS ((PF4 / PF_PER_T + 255) / 256)      // 733
__global__ void k_esum_g(const int4* __restrict__ src4, const int4* __restrict__ dst4,
                         int E4, const float* __restrict__ attn_l,
                         const float4* __restrict__ input) {
    if (blockIdx.x < PF_BLOCKS) {
        // ---- prefetch path: touch lines into L2 (skip L1), keep result live
        int t = blockIdx.x * 256 + threadIdx.x;
        float acc = 0.f;
#pragma unroll
        for (int j = 0; j < PF_PER_T; j++) {
            int idx = t * PF_PER_T + j;
            if (idx < PF4) {
                float4 v = __ldcg(&input[idx]);
                acc += v.x + v.y + v.z + v.w;
            }
        }
        if (acc == 1.2345e38f) g_sink = acc;   // never true; blocks DCE
        return;
    }

    float a0 = __ldg(&attn_l[0]);
    float a1 = __ldg(&attn_l[1]);
    int i = (blockIdx.x - PF_BLOCKS) * blockDim.x + threadIdx.x;
    int base = i * 2;
    if (base >= E4) return;

    int4 s0 = __ldcs(&src4[base]);
    int4 d0 = __ldcs(&dst4[base]);
    int4 s1 = __ldcs(&src4[base + 1]);
    int4 d1 = __ldcs(&dst4[base + 1]);

    int ss[8] = {s0.x, s0.y, s0.z, s0.w, s1.x, s1.y, s1.z, s1.w};
    int dd[8] = {d0.x, d0.y, d0.z, d0.w, d1.x, d1.y, d1.z, d1.w};

    float2 z[8];
    float  erd[8];
#pragma unroll
    for (int j = 0; j < 8; j++) {
        z[j]   = __ldg(&g_z[ss[j]]);
        erd[j] = __ldg(&g_er[dd[j]]);
    }
#pragma unroll
    for (int j = 0; j < 8; j++) {
        float e = fmaf(z[j].x, a0, fmaf(z[j].y, a1, erd[j]));
        e = (e > 0.f) ? e : 0.2f * e;        // leaky_relu(0.2)
        float ex = __expf(e);
        atomicAdd(&g_acc[dd[j]], make_float4(ex, ex * z[j].x, ex * z[j].y, 0.f));
    }
}

// K3 (fused epilogue + gate + scale):
// out[i,h] = input[i,h] * sigmoid(x[i]*relu(coff0) + relu(coff1)),
// coff = num/denom + bias recomputed per thread from g_acc (L2-resident).
// CTA order REVERSED: first-scheduled blocks read gemm-warm high addresses,
// last-scheduled read the prefetch-warm low addresses.
#define TOT4 (NN * (HH / 4))                 // 6,400,000 float4s
__global__ void k_out(const float4* __restrict__ input, float4* __restrict__ out,
                      const float* __restrict__ x, const float* __restrict__ bias) {
    const int half = TOT4 / 2;               // 3,200,000
    int b = (int)gridDim.x - 1 - (int)blockIdx.x;      // reverse traversal
    int i = b * (int)blockDim.x + (int)threadIdx.x;
    if (i >= half) return;
    int i2 = i + half;

    float b0 = __ldg(&bias[0]);
    float b1 = __ldg(&bias[1]);

    int r0 = i  >> 6;                        // 64 float4 per row
    int r1 = i2 >> 6;

    float4 v0 = __ldcs(&input[i2]);          // highest addresses first (hotter)
    float4 v1 = __ldcs(&input[i]);
    float4 a0 = __ldg(&g_acc[r1]);
    float4 a1 = __ldg(&g_acc[r0]);
    float  x0 = __ldg(&x[r1]);
    float  x1 = __ldg(&x[r0]);

    float inv0 = 1.f / a0.x;
    float c00 = a0.y * inv0 + b0, c01 = a0.z * inv0 + b1;
    float arg0 = fmaf(x0, fmaxf(c00, 0.f), fmaxf(c01, 0.f));
    float s0 = 1.f / (1.f + __expf(-arg0));

    float inv1 = 1.f / a1.x;
    float c10 = a1.y * inv1 + b0, c11 = a1.z * inv1 + b1;
    float arg1 = fmaf(x1, fmaxf(c10, 0.f), fmaxf(c11, 0.f));
    float s1 = 1.f / (1.f + __expf(-arg1));

    v0.x *= s0; v0.y *= s0; v0.z *= s0; v0.w *= s0;
    v1.x *= s1; v1.y *= s1; v1.z *= s1; v1.w *= s1;
    __stcs(&out[i2], v0);
    __stcs(&out[i],  v1);
}

extern "C" void kernel_launch(void* const* d_in, const int* in_sizes, int n_in,
                              void* d_out, int out_size) {
    const float* input  = (const float*)d_in[0];
    const float* x      = (const float*)d_in[1];
    // d_in[2] = degree (unused)
    const int*   esrc   = (const int*)d_in[3];
    const int*   edst   = (const int*)d_in[4];
    const float* W      = (const float*)d_in[5];
    const float* attn_l = (const float*)d_in[6];
    const float* attn_r = (const float*)d_in[7];
    const float* bias   = (const float*)d_in[8];
    float* out = (float*)d_out;

    int E  = in_sizes[3];
    int E4 = E / 4;            // 800,000 int4s per edge array
    int nE = (E4 + 1) / 2;     // threads processing 2 int4 each
    int eBlocks = (nE + 255) / 256;

    k_gemm<<<(NN + 31) / 32, 256>>>(input, W, attn_r);
    k_esum_g<<<PF_BLOCKS + eBlocks, 256>>>((const int4*)esrc, (const int4*)edst,
                                           E4, attn_l, (const float4*)input);
    k_out<<<(TOT4 / 2 + 255) / 256, 256>>>((const float4*)input, (float4*)out, x, bias);
}

// round 10
// speedup vs baseline: 1.0867x; 1.0682x over previous
#include <cuda_runtime.h>
#include <cuda_bf16.h>

#define NN 100000
#define HH 256

// Per-node scratch (device globals: no allocation allowed in kernel_launch)
__device__ float4   g_zl[NN];        // {z0, z1, el, pad} per node (src-side gather)
__device__ float    g_er[NN];        // z . attn_r (dest term) — separate read-only
                                     // array (R5: co-locating with atomic target
                                     // caused sector-RMW contention)
__device__ float4   g_acc[NN];       // {denom, num0, num1, pad}

// K1: 4-lanes-per-node GEMM [N,256]@[256,2] -> zl, er; init accumulators.
// 256 threads = 64 nodes/block, 16 float4 loads per lane (high MLP), 64B
// contiguous per 4-lane group (2 full sectors), 2-level shuffle reduction.
__global__ void k_gemm(const float* __restrict__ input,
                       const float* __restrict__ W,
                       const float* __restrict__ attn_l,
                       const float* __restrict__ attn_r) {
    __shared__ float sw0[HH], sw1[HH];
    int t = threadIdx.x;
    { sw0[t] = W[t * 2 + 0]; sw1[t] = W[t * 2 + 1]; }   // t covers 0..255 == HH
    __syncthreads();

    int grp = t >> 2, gl = t & 3;
    int node = blockIdx.x * 64 + grp;
    if (node >= NN) return;

    const float4* row4 = (const float4*)(input + (size_t)node * HH);
    float d0 = 0.f, d1 = 0.f;
#pragma unroll
    for (int j = 0; j < 16; j++) {
        int k = j * 4 + gl;                  // lanes 0..3 -> contiguous 64B
        float4 v = row4[k];
        int b = 4 * k;
        d0 = fmaf(v.x, sw0[b+0], d0); d1 = fmaf(v.x, sw1[b+0], d1);
        d0 = fmaf(v.y, sw0[b+1], d0); d1 = fmaf(v.y, sw1[b+1], d1);
        d0 = fmaf(v.z, sw0[b+2], d0); d1 = fmaf(v.z, sw1[b+2], d1);
        d0 = fmaf(v.w, sw0[b+3], d0); d1 = fmaf(v.w, sw1[b+3], d1);
    }
#pragma unroll
    for (int o = 2; o; o >>= 1) {
        d0 += __shfl_xor_sync(0xFFFFFFFFu, d0, o);
        d1 += __shfl_xor_sync(0xFFFFFFFFu, d1, o);
    }
    if (gl == 0) {
        float el = d0 * attn_l[0] + d1 * attn_l[1];
        float er = d0 * attn_r[0] + d1 * attn_r[1];
        g_zl[node]  = make_float4(d0, d1, el, 0.f);
        g_er[node]  = er;
        g_acc[node] = make_float4(0.f, 0.f, 0.f, 0.f);
    }
}

// K2: per-edge softmax accumulation WITHOUT max-subtraction (shift-invariant;
// e is bounded far inside fp32 exp range for this distribution).
// 8 edges/thread; evict-first edge streams so they don't flush warm L2.
__global__ void k_esum_g(const int4* __restrict__ src4, const int4* __restrict__ dst4,
                         int E4) {
    int i = blockIdx.x * blockDim.x + threadIdx.x;
    int base = i * 2;
    if (base >= E4) return;

    int4 s0 = __ldcs(&src4[base]);
    int4 d0 = __ldcs(&dst4[base]);
    int4 s1 = __ldcs(&src4[base + 1]);
    int4 d1 = __ldcs(&dst4[base + 1]);

    int ss[8] = {s0.x, s0.y, s0.z, s0.w, s1.x, s1.y, s1.z, s1.w};
    int dd[8] = {d0.x, d0.y, d0.z, d0.w, d1.x, d1.y, d1.z, d1.w};

    float4 z[8];
    float  erd[8];
#pragma unroll
    for (int j = 0; j < 8; j++) {
        z[j]   = __ldg(&g_zl[ss[j]]);        // {z0, z1, el, -}
        erd[j] = __ldg(&g_er[dd[j]]);
    }
#pragma unroll
    for (int j = 0; j < 8; j++) {
        float e = z[j].z + erd[j];
        e = (e > 0.f) ? e : 0.2f * e;        // leaky_relu(0.2)
        float ex = __expf(e);
        atomicAdd(&g_acc[dd[j]], make_float4(ex, ex * z[j].x, ex * z[j].y, 0.f));
    }
}

// K3 (fused epilogue + gate + scale):
// out[i,h] = input[i,h] * sigmoid(x[i]*relu(coff0) + relu(coff1)),
// coff = num/denom + bias recomputed per thread from g_acc (L2-resident).
// CTA order REVERSED: first-scheduled blocks read the input rows most
// recently cached by k_gemm (races the LRU eviction front).
#define TOT4 (NN * (HH / 4))                 // 6,400,000 float4s
__global__ void k_out(const float4* __restrict__ input, float4* __restrict__ out,
                      const float* __restrict__ x, const float* __restrict__ bias) {
    const int half = TOT4 / 2;               // 3,200,000
    int b = (int)gridDim.x - 1 - (int)blockIdx.x;      // reverse traversal
    int i = b * (int)blockDim.x + (int)threadIdx.x;
    if (i >= half) return;
    int i2 = i + half;

    float b0 = __ldg(&bias[0]);
    float b1 = __ldg(&bias[1]);

    int r0 = i  >> 6;                        // 64 float4 per row
    int r1 = i2 >> 6;

    float4 v0 = __ldcs(&input[i2]);          // highest addresses first (hotter)
    float4 v1 = __ldcs(&input[i]);
    float4 a0 = __ldg(&g_acc[r1]);
    float4 a1 = __ldg(&g_acc[r0]);
    float  x0 = __ldg(&x[r1]);
    float  x1 = __ldg(&x[r0]);

    float inv0 = 1.f / a0.x;
    float c00 = a0.y * inv0 + b0, c01 = a0.z * inv0 + b1;
    float arg0 = fmaf(x0, fmaxf(c00, 0.f), fmaxf(c01, 0.f));
    float s0 = 1.f / (1.f + __expf(-arg0));

    float inv1 = 1.f / a1.x;
    float c10 = a1.y * inv1 + b0, c11 = a1.z * inv1 + b1;
    float arg1 = fmaf(x1, fmaxf(c10, 0.f), fmaxf(c11, 0.f));
    float s1 = 1.f / (1.f + __expf(-arg1));

    v0.x *= s0; v0.y *= s0; v0.z *= s0; v0.w *= s0;
    v1.x *= s1; v1.y *= s1; v1.z *= s1; v1.w *= s1;
    __stcs(&out[i2], v0);
    __stcs(&out[i],  v1);
}

extern "C" void kernel_launch(void* const* d_in, const int* in_sizes, int n_in,
                              void* d_out, int out_size) {
    const float* input  = (const float*)d_in[0];
    const float* x      = (const float*)d_in[1];
    // d_in[2] = degree (unused)
    const int*   esrc   = (const int*)d_in[3];
    const int*   edst   = (const int*)d_in[4];
    const float* W      = (const float*)d_in[5];
    const float* attn_l = (const float*)d_in[6];
    const float* attn_r = (const float*)d_in[7];
    const float* bias   = (const float*)d_in[8];
    float* out = (float*)d_out;

    int E  = in_sizes[3];
    int E4 = E / 4;            // 800,000 int4s per edge array
    int nE = (E4 + 1) / 2;     // threads processing 2 int4 each

    k_gemm<<<(NN + 63) / 64, 256>>>(input, W, attn_l, attn_r);
    k_esum_g<<<(nE + 255) / 256, 256>>>((const int4*)esrc, (const int4*)edst, E4);
    k_out<<<(TOT4 / 2 + 255) / 256, 256>>>((const float4*)input, (float4*)out, x, bias);
}

// round 11
// speedup vs baseline: 1.0911x; 1.0041x over previous
#include <cuda_runtime.h>
#include <cuda_bf16.h>

#define NN 100000
#define HH 256

// Per-node scratch (device globals: no allocation allowed in kernel_launch)
__device__ float4   g_zl[NN];        // {z0, z1, el, pad} per node (src-side gather)
__device__ float    g_er[NN];        // z . attn_r (dest term) — separate read-only
                                     // array (R5: co-locating with atomic target
                                     // caused sector-RMW contention)
__device__ float4   g_acc[NN];       // {denom, num0, num1, pad}

// K1: 8-lanes-per-node GEMM [N,256]@[256,2] -> zl, er; init accumulators.
// (R9 shape — measured 20.0us: full 128B line per 8-lane group, 8 float4/lane.)
__global__ void k_gemm(const float* __restrict__ input,
                       const float* __restrict__ W,
                       const float* __restrict__ attn_l,
                       const float* __restrict__ attn_r) {
    __shared__ float sw0[HH], sw1[HH];
    int t = threadIdx.x;
    { sw0[t] = W[t * 2 + 0]; sw1[t] = W[t * 2 + 1]; }   // t covers 0..255 == HH
    __syncthreads();

    int grp = t >> 3, gl = t & 7;
    int node = blockIdx.x * 32 + grp;
    if (node >= NN) return;

    const float4* row4 = (const float4*)(input + (size_t)node * HH);
    float d0 = 0.f, d1 = 0.f;
#pragma unroll
    for (int j = 0; j < 8; j++) {
        int k = j * 8 + gl;                  // lanes 0..7 -> contiguous 128B line
        float4 v = row4[k];
        int b = 4 * k;
        d0 = fmaf(v.x, sw0[b+0], d0); d1 = fmaf(v.x, sw1[b+0], d1);
        d0 = fmaf(v.y, sw0[b+1], d0); d1 = fmaf(v.y, sw1[b+1], d1);
        d0 = fmaf(v.z, sw0[b+2], d0); d1 = fmaf(v.z, sw1[b+2], d1);
        d0 = fmaf(v.w, sw0[b+3], d0); d1 = fmaf(v.w, sw1[b+3], d1);
    }
#pragma unroll
    for (int o = 4; o; o >>= 1) {
        d0 += __shfl_xor_sync(0xFFFFFFFFu, d0, o);
        d1 += __shfl_xor_sync(0xFFFFFFFFu, d1, o);
    }
    if (gl == 0) {
        float el = d0 * attn_l[0] + d1 * attn_l[1];
        float er = d0 * attn_r[0] + d1 * attn_r[1];
        g_zl[node]  = make_float4(d0, d1, el, 0.f);
        g_er[node]  = er;
        g_acc[node] = make_float4(0.f, 0.f, 0.f, 0.f);
    }
}

// K2: per-edge softmax accumulation WITHOUT max-subtraction (shift-invariant;
// e is bounded far inside fp32 exp range for this distribution).
// 8 edges/thread; evict-first edge streams so they don't flush warm L2.
__global__ void k_esum_g(const int4* __restrict__ src4, const int4* __restrict__ dst4,
                         int E4) {
    int i = blockIdx.x * blockDim.x + threadIdx.x;
    int base = i * 2;
    if (base >= E4) return;

    int4 s0 = __ldcs(&src4[base]);
    int4 d0 = __ldcs(&dst4[base]);
    int4 s1 = __ldcs(&src4[base + 1]);
    int4 d1 = __ldcs(&dst4[base + 1]);

    int ss[8] = {s0.x, s0.y, s0.z, s0.w, s1.x, s1.y, s1.z, s1.w};
    int dd[8] = {d0.x, d0.y, d0.z, d0.w, d1.x, d1.y, d1.z, d1.w};

    float4 z[8];
    float  erd[8];
#pragma unroll
    for (int j = 0; j < 8; j++) {
        z[j]   = __ldg(&g_zl[ss[j]]);        // {z0, z1, el, -}
        erd[j] = __ldg(&g_er[dd[j]]);
    }
#pragma unroll
    for (int j = 0; j < 8; j++) {
        float e = z[j].z + erd[j];
        e = (e > 0.f) ? e : 0.2f * e;        // leaky_relu(0.2)
        float ex = __expf(e);
        atomicAdd(&g_acc[dd[j]], make_float4(ex, ex * z[j].x, ex * z[j].y, 0.f));
    }
}

// K3 (fused epilogue + gate + scale):
// Each block owns 512 contiguous float4s = 8 rows. Threads 0-7 compute the 8
// gate scalars ONCE into smem (32x fewer g_acc/x sector reads than per-thread
// recompute), then all threads apply them. Block order REVERSED so the first-
// scheduled blocks read the input rows most recently cached by k_gemm.
#define TOT4 (NN * (HH / 4))                 // 6,400,000 float4s = 12500 * 512
__global__ void k_out(const float4* __restrict__ input, float4* __restrict__ out,
                      const float* __restrict__ x, const float* __restrict__ bias) {
    __shared__ float ssc[8];
    int b = (int)gridDim.x - 1 - (int)blockIdx.x;      // reverse traversal
    int base = b * 512;                      // first float4 of this block
    int t = threadIdx.x;

    if (t < 8) {
        int row = (base >> 6) + t;           // 64 float4 per row
        float4 a = __ldg(&g_acc[row]);
        float  xv = __ldg(&x[row]);
        float b0 = __ldg(&bias[0]);
        float b1 = __ldg(&bias[1]);
        float inv = 1.f / a.x;
        float c0 = a.y * inv + b0;
        float c1 = a.z * inv + b1;
        float arg = fmaf(xv, fmaxf(c0, 0.f), fmaxf(c1, 0.f));
        ssc[t] = 1.f / (1.f + __expf(-arg));
    }
    __syncthreads();

    int i1 = base + t;                       // rows 0..3 of the block
    int i2 = base + t + 256;                 // rows 4..7 of the block
    float4 v1 = __ldcs(&input[i1]);
    float4 v2 = __ldcs(&input[i2]);
    float s1 = ssc[t >> 6];
    float s2 = ssc[4 + (t >> 6)];
    v1.x *= s1; v1.y *= s1; v1.z *= s1; v1.w *= s1;
    v2.x *= s2; v2.y *= s2; v2.z *= s2; v2.w *= s2;
    __stcs(&out[i1], v1);
    __stcs(&out[i2], v2);
}

extern "C" void kernel_launch(void* const* d_in, const int* in_sizes, int n_in,
                              void* d_out, int out_size) {
    const float* input  = (const float*)d_in[0];
    const float* x      = (const float*)d_in[1];
    // d_in[2] = degree (unused)
    const int*   esrc   = (const int*)d_in[3];
    const int*   edst   = (const int*)d_in[4];
    const float* W      = (const float*)d_in[5];
    const float* attn_l = (const float*)d_in[6];
    const float* attn_r = (const float*)d_in[7];
    const float* bias   = (const float*)d_in[8];
    float* out = (float*)d_out;

    int E  = in_sizes[3];
    int E4 = E / 4;            // 800,000 int4s per edge array
    int nE = (E4 + 1) / 2;     // threads processing 2 int4 each

    k_gemm<<<(NN + 31) / 32, 256>>>(input, W, attn_l, attn_r);
    k_esum_g<<<(nE + 255) / 256, 256>>>((const int4*)esrc, (const int4*)edst, E4);
    k_out<<<TOT4 / 512, 256>>>((const float4*)input, (float4*)out, x, bias);
}